// round 13
// baseline (speedup 1.0000x reference)
#include <cuda_runtime.h>
#include <cuda_fp16.h>
#include <math.h>
#include <stdint.h>

#define BB  128   // batch
#define TT  512   // time
#define II  300   // input dim
#define HH  150   // hidden per dir
#define G3  450   // 3*H
#define KK  6     // topics
#define CC  300   // attn context dim
#define THD 20    // topic hidden
#define NCLS 5
#define D2  300   // 2*H

#define MM    (BB*TT)   // 65536 GEMM rows
#define KPAD  320       // K padded
#define NPAD  1024      // 2 dirs x 512 padded cols

// ---------------- scratch (device globals; no allocations allowed) ----------
__device__ __half g_gih[2][TT][BB][G3];   // input projections fp16 (118 MB)
__device__ float g_seq[BB][TT][D2];       // bi-GRU outputs
__device__ float g_hidden[BB][D2];        // final hidden states
__device__ float g_ctxbase[KK][D2];       // batch-independent part of context
__device__ float g_context[BB][KK][D2];   // tanh context
__device__ float g_regpart[BB];
__device__ __half g_xh[(size_t)MM * KPAD];   // fp16 x, padded (40 MB)
__device__ __half g_wp[(size_t)NPAD * KPAD]; // fp16 Wih both dirs, padded
__device__ float  g_bihp[NPAD];              // padded bias (both dirs)

// ===================== PTX helpers ==========================================
__device__ __forceinline__ uint32_t smem_u32(const void* p) {
    uint32_t a;
    asm("{ .reg .u64 t; cvta.to.shared.u64 t, %1; cvt.u32.u64 %0, t; }" : "=r"(a) : "l"(p));
    return a;
}
__device__ __forceinline__ void cpasync16(uint32_t dst, const void* src) {
    asm volatile("cp.async.cg.shared.global [%0], [%1], 16;" :: "r"(dst), "l"(src));
}
__device__ __forceinline__ void cp_commit() { asm volatile("cp.async.commit_group;" ::: "memory"); }
template<int N> __device__ __forceinline__ void cp_waitg() {
    asm volatile("cp.async.wait_group %0;" :: "n"(N) : "memory");
}
__device__ __forceinline__ void ldm4(uint32_t* r, uint32_t addr) {
    asm volatile("ldmatrix.sync.aligned.m8n8.x4.shared.b16 {%0,%1,%2,%3}, [%4];"
                 : "=r"(r[0]), "=r"(r[1]), "=r"(r[2]), "=r"(r[3]) : "r"(addr));
}
__device__ __forceinline__ void ldm2(uint32_t* r, uint32_t addr) {
    asm volatile("ldmatrix.sync.aligned.m8n8.x2.shared.b16 {%0,%1}, [%2];"
                 : "=r"(r[0]), "=r"(r[1]) : "r"(addr));
}
__device__ __forceinline__ void mma16816(float* d, const uint32_t* a, uint32_t b0, uint32_t b1) {
    asm volatile("mma.sync.aligned.m16n8k16.row.col.f32.f16.f16.f32 "
                 "{%0,%1,%2,%3}, {%4,%5,%6,%7}, {%8,%9}, {%0,%1,%2,%3};"
                 : "+f"(d[0]), "+f"(d[1]), "+f"(d[2]), "+f"(d[3])
                 : "r"(a[0]), "r"(a[1]), "r"(a[2]), "r"(a[3]), "r"(b0), "r"(b1));
}
__device__ __forceinline__ float fast_sigmoid(float x) {
    float e, r;
    asm("ex2.approx.f32 %0, %1;" : "=f"(e) : "f"(-1.4426950408889634f * x));
    asm("rcp.approx.f32 %0, %1;" : "=f"(r) : "f"(1.0f + e));
    return r;
}
__device__ __forceinline__ float fast_tanh(float x) {
    float e, r;
    asm("ex2.approx.f32 %0, %1;" : "=f"(e) : "f"(2.8853900817779268f * x));
    asm("rcp.approx.f32 %0, %1;" : "=f"(r) : "f"(1.0f + e));
    return 1.0f - 2.0f * r;
}

// ===================== conversion kernels ===================================
__global__ void k_convA(const float* __restrict__ x) {
    int i = blockIdx.x * 256 + threadIdx.x;
    if (i >= MM * (KPAD / 2)) return;
    int m = i / (KPAD / 2), c2 = i % (KPAD / 2), k = c2 * 2;
    float a = (k < II)     ? x[(size_t)m * II + k]     : 0.f;
    float b = (k + 1 < II) ? x[(size_t)m * II + k + 1] : 0.f;
    ((__half2*)g_xh)[(size_t)m * (KPAD / 2) + c2] = __floats2half2_rn(a, b);
}
__global__ void k_convB(const float* __restrict__ Wf, const float* __restrict__ Wb) {
    int i = blockIdx.x * 256 + threadIdx.x;
    if (i >= NPAD * (KPAD / 2)) return;
    int jg = i / (KPAD / 2), c2 = i % (KPAD / 2), k = c2 * 2;
    int dir = jg >> 9, j = jg & 511;
    const float* W = dir ? Wb : Wf;
    float a = 0.f, b = 0.f;
    if (j < G3) {
        if (k < II)     a = W[(size_t)j * II + k];
        if (k + 1 < II) b = W[(size_t)j * II + k + 1];
    }
    ((__half2*)g_wp)[(size_t)jg * (KPAD / 2) + c2] = __floats2half2_rn(a, b);
}
__global__ void k_convBias(const float* __restrict__ bf, const float* __restrict__ bb) {
    int jg = blockIdx.x * 256 + threadIdx.x;
    if (jg >= NPAD) return;
    int dir = jg >> 9, j = jg & 511;
    g_bihp[jg] = (j < G3) ? (dir ? bb[j] : bf[j]) : 0.f;
}

// ===================== K1: mma.sync GEMM gi = x @ W^T + b ===================
#define BM  128
#define BN  128
#define BKC 32
#define LDA 40                // halves per smem row (32 + 8 pad)
#define NSTG (KPAD / BKC)     // 10 k-stages
#define PSTG 4                // pipeline depth
#define STG_BYTES ((BM + BN) * LDA * 2)       // 20480 B per stage
#define GEMM_SMEM (PSTG * STG_BYTES)          // 81920 B

__global__ void __launch_bounds__(256, 2) k_gemm() {
    extern __shared__ __align__(16) char gsm[];

    const int tid = threadIdx.x, wid = tid >> 5, lane = tid & 31;
    const int wm = wid & 3, wn = wid >> 2;
    const int m0 = blockIdx.x * BM, n0 = blockIdx.y * BN;

    float acc[2][8][4];
#pragma unroll
    for (int mi = 0; mi < 2; mi++)
#pragma unroll
        for (int nj = 0; nj < 8; nj++)
#pragma unroll
            for (int e = 0; e < 4; e++) acc[mi][nj][e] = 0.f;

    uint32_t sAb[PSTG], sBb[PSTG];
#pragma unroll
    for (int s = 0; s < PSTG; s++) {
        sAb[s] = smem_u32(gsm + s * STG_BYTES);
        sBb[s] = sAb[s] + BM * LDA * 2;
    }

    auto load_stage = [&](int ks, int buf) {
        int k0 = ks * BKC;
#pragma unroll
        for (int i = 0; i < 2; i++) {
            int idx = tid + i * 256;
            int row = idx >> 2, seg = idx & 3;
            cpasync16(sAb[buf] + (uint32_t)(row * LDA + seg * 8) * 2,
                      g_xh + (size_t)(m0 + row) * KPAD + k0 + seg * 8);
            cpasync16(sBb[buf] + (uint32_t)(row * LDA + seg * 8) * 2,
                      g_wp + (size_t)(n0 + row) * KPAD + k0 + seg * 8);
        }
    };

    load_stage(0, 0); cp_commit();
    load_stage(1, 1); cp_commit();
    load_stage(2, 2); cp_commit();

    const int a_row = (lane & 15);
    const int a_col8 = (lane >> 4) * 8;
    const int b_nrow = ((lane >> 4) * 8) + (lane & 7);
    const int b_col8 = ((lane >> 3) & 1) * 8;

#pragma unroll
    for (int ks = 0; ks < NSTG; ks++) {
        if (ks <= NSTG - 3)      cp_waitg<2>();
        else if (ks == NSTG - 2) cp_waitg<1>();
        else                     cp_waitg<0>();
        __syncthreads();
        if (ks + 3 < NSTG) { load_stage(ks + 3, (ks + 3) & 3); cp_commit(); }
        int buf = ks & 3;
#pragma unroll
        for (int s = 0; s < 2; s++) {
            uint32_t a[2][4], bfr[4][4];
#pragma unroll
            for (int mi = 0; mi < 2; mi++) {
                uint32_t addr = sAb[buf] +
                    (uint32_t)(((wm * 32 + mi * 16 + a_row) * LDA) + s * 16 + a_col8) * 2;
                ldm4(a[mi], addr);
            }
#pragma unroll
            for (int nj = 0; nj < 4; nj++) {
                uint32_t addr = sBb[buf] +
                    (uint32_t)(((wn * 64 + nj * 16 + b_nrow) * LDA) + s * 16 + b_col8) * 2;
                ldm4(bfr[nj], addr);
            }
#pragma unroll
            for (int mi = 0; mi < 2; mi++)
#pragma unroll
                for (int nj = 0; nj < 4; nj++) {
                    mma16816(acc[mi][2 * nj],     a[mi], bfr[nj][0], bfr[nj][1]);
                    mma16816(acc[mi][2 * nj + 1], a[mi], bfr[nj][2], bfr[nj][3]);
                }
        }
    }

    const int g = lane >> 2, tig = lane & 3;
#pragma unroll
    for (int mi = 0; mi < 2; mi++)
#pragma unroll
        for (int nj = 0; nj < 8; nj++) {
            int coln = wn * 64 + nj * 8 + tig * 2;
            int jglob = n0 + coln;
            int dir = jglob >> 9, jj = jglob & 511;
            if (jj < G3) {
                float bia0 = g_bihp[jglob], bia1 = g_bihp[jglob + 1];
#pragma unroll
                for (int h = 0; h < 2; h++) {
                    int m = m0 + wm * 32 + mi * 16 + g + h * 8;
                    int b = m >> 9, t = m & 511;
                    int ts = dir ? (TT - 1 - t) : t;
                    *(__half2*)&g_gih[dir][ts][b][jj] =
                        __floats2half2_rn(acc[mi][nj][2 * h] + bia0,
                                          acc[mi][nj][2 * h + 1] + bia1);
                }
            }
        }
}

// ======================= K2: GRU recurrence (fused gates in MMA lanes) ======
// 128 CTAs (dir*64 + pair), 480 threads = 15 warps. Whh rows PERMUTED so that
// warp w's 32 rows are the (r,z,n) triples of gates jj in [10w,10w+10):
//   rloc g / g+8 / g+16  (g<8)  -> r/z/n of gate 10w+g  (all on lane 4g)
//   rloc 24..29           -> r8,z8,n8,r9,z9,n9 (gates 8,9 via shfl)
// A-fragments built once from global fp32 Whh. h double-buffered in smem;
// ONE barrier per step; gates computed in-register by the MMA lanes.
#define LDS_H 168
__device__ __forceinline__ int maprow(int w, int rloc) {
    if (rloc < 24) return 10 * w + (rloc & 7) + HH * (rloc >> 3);
    if (rloc < 30) { int s = rloc - 24; return 10 * w + 8 + (s / 3) + HH * (s % 3); }
    return -1;
}

__global__ void __launch_bounds__(480, 1) k_rec(
    const float* __restrict__ Whh_f, const float* __restrict__ bhh_f,
    const float* __restrict__ Whh_b, const float* __restrict__ bhh_b)
{
    __shared__ __half sh[2][8][LDS_H];        // [buf][batch(n)][k]

    const int tid = threadIdx.x, wid = tid >> 5, lane = tid & 31;
    const int blk = blockIdx.x;
    const int dir = blk >> 6;
    const int b0  = (blk & 63) * 2;
    const float* Whh = dir ? Whh_b : Whh_f;
    const float* bhh = dir ? bhh_b : bhh_f;

    // zero both h buffers
    for (int idx = tid; idx < 2 * 8 * LDS_H; idx += 480)
        ((__half*)sh)[idx] = __float2half(0.f);

    // ---- build A fragments directly from global Whh (permuted rows) ----
    const int g = lane >> 2;                   // 0..7
    const int cp2 = (lane & 3) * 2;            // col pair base
    uint32_t afr[2][10][4];
#pragma unroll
    for (int mt = 0; mt < 2; mt++) {
        int rlo = maprow(wid, mt * 16 + g);
        int rhi = maprow(wid, mt * 16 + g + 8);
#pragma unroll
        for (int kt = 0; kt < 10; kt++) {
#pragma unroll
            for (int e = 0; e < 4; e++) {
                int row = (e & 1) ? rhi : rlo;
                int col = kt * 16 + cp2 + ((e & 2) ? 8 : 0);
                float f0 = (row >= 0 && col < HH)     ? Whh[row * HH + col]     : 0.f;
                float f1 = (row >= 0 && col + 1 < HH) ? Whh[row * HH + col + 1] : 0.f;
                __half2 hv = __floats2half2_rn(f0, f1);
                afr[mt][kt][e] = *(uint32_t*)&hv;
            }
        }
    }
    // bias for rows {g, g+8, g+16, g+24}
    float bias[4];
#pragma unroll
    for (int e = 0; e < 4; e++) {
        int r = maprow(wid, e * 8 + g);
        bias[e] = (r >= 0) ? bhh[r] : 0.f;
    }

    // B (h) ldmatrix lane addresses, both buffers
    int hrow = (lane < 8) ? lane : ((lane < 16) ? (lane - 8) : 0);
    int hcol = (lane >= 8 && lane < 16) ? 8 : 0;
    const uint32_t hb[2] = { smem_u32(&sh[0][hrow][hcol]), smem_u32(&sh[1][hrow][hcol]) };

    // gate ownership
    const bool isg  = (lane & 3) == 0;        // gate jjp = 10w+g
    const int  jjp  = 10 * wid + g;
    const bool hasE = (lane == 0) || (lane == 12);
    const int  jje  = 10 * wid + ((lane == 0) ? 8 : 9);

    const __half* gi = &g_gih[dir][0][0][0];
    __half pp[6], pe[6];
    auto prefetch = [&](int t) {
        if (isg) {
            long o = ((long)t * BB + b0) * G3 + jjp;
            pp[0] = gi[o]; pp[1] = gi[o + HH]; pp[2] = gi[o + 2 * HH];
            pp[3] = gi[o + G3]; pp[4] = gi[o + G3 + HH]; pp[5] = gi[o + G3 + 2 * HH];
        }
        if (hasE) {
            long o = ((long)t * BB + b0) * G3 + jje;
            pe[0] = gi[o]; pe[1] = gi[o + HH]; pe[2] = gi[o + 2 * HH];
            pe[3] = gi[o + G3]; pe[4] = gi[o + G3 + HH]; pe[5] = gi[o + G3 + 2 * HH];
        }
    };
    prefetch(0);
    float h0p = 0.f, h1p = 0.f, h0e = 0.f, h1e = 0.f;
    __syncthreads();

    for (int t = 0; t < TT; t++) {
        const int par = t & 1, nxt = par ^ 1;
        float acc0[4] = { bias[0], bias[0], bias[1], bias[1] };
        float acc1[4] = { bias[2], bias[2], bias[3], bias[3] };
#pragma unroll
        for (int kt = 0; kt < 10; kt++) {
            uint32_t bfr[2];
            ldm2(bfr, hb[par] + kt * 32);
            mma16816(acc0, afr[0][kt], bfr[0], bfr[1]);
            mma16816(acc1, afr[1][kt], bfr[0], bfr[1]);
        }
        // gather z/n rows of gates 8,9 (rows 25,26 / 28,29 live on lanes +4,+8)
        float sz0 = __shfl_down_sync(0xffffffffu, acc1[2], 4);
        float sz1 = __shfl_down_sync(0xffffffffu, acc1[3], 4);
        float sn0 = __shfl_down_sync(0xffffffffu, acc1[2], 8);
        float sn1 = __shfl_down_sync(0xffffffffu, acc1[3], 8);

        // consume prefetched gi, then prefetch next step
        float gr0 = __half2float(pp[0]), gz0 = __half2float(pp[1]), gn0 = __half2float(pp[2]);
        float gr1 = __half2float(pp[3]), gz1 = __half2float(pp[4]), gn1 = __half2float(pp[5]);
        float er0 = __half2float(pe[0]), ez0 = __half2float(pe[1]), en0 = __half2float(pe[2]);
        float er1 = __half2float(pe[3]), ez1 = __half2float(pe[4]), en1 = __half2float(pe[5]);
        if (t + 1 < TT) prefetch(t + 1);

        const int tw = dir ? (TT - 1 - t) : t;
        if (isg) {
            float r0 = fast_sigmoid(acc0[0] + gr0);
            float z0 = fast_sigmoid(acc0[2] + gz0);
            float n0 = fast_tanh(gn0 + r0 * acc1[0]);
            h0p = (1.f - z0) * n0 + z0 * h0p;
            float r1 = fast_sigmoid(acc0[1] + gr1);
            float z1 = fast_sigmoid(acc0[3] + gz1);
            float n1 = fast_tanh(gn1 + r1 * acc1[1]);
            h1p = (1.f - z1) * n1 + z1 * h1p;
            sh[nxt][0][jjp] = __float2half(h0p);
            sh[nxt][1][jjp] = __float2half(h1p);
            g_seq[b0][tw][dir * HH + jjp]     = h0p;
            g_seq[b0 + 1][tw][dir * HH + jjp] = h1p;
        }
        if (hasE) {
            float r0 = fast_sigmoid(acc1[2] + er0);
            float z0 = fast_sigmoid(sz0 + ez0);
            float n0 = fast_tanh(en0 + r0 * sn0);
            h0e = (1.f - z0) * n0 + z0 * h0e;
            float r1 = fast_sigmoid(acc1[3] + er1);
            float z1 = fast_sigmoid(sz1 + ez1);
            float n1 = fast_tanh(en1 + r1 * sn1);
            h1e = (1.f - z1) * n1 + z1 * h1e;
            sh[nxt][0][jje] = __float2half(h0e);
            sh[nxt][1][jje] = __float2half(h1e);
            g_seq[b0][tw][dir * HH + jje]     = h0e;
            g_seq[b0 + 1][tw][dir * HH + jje] = h1e;
        }
        __syncthreads();      // h[nxt] complete; everyone done reading h[par]
    }
    if (isg) {
        g_hidden[b0][dir * HH + jjp]     = h0p;
        g_hidden[b0 + 1][dir * HH + jjp] = h1p;
    }
    if (hasE) {
        g_hidden[b0][dir * HH + jje]     = h0e;
        g_hidden[b0 + 1][dir * HH + jje] = h1e;
    }
}

// ============== K3a: batch-independent part of attention context ============
__global__ void k_ctxbase(const float* __restrict__ ac, const float* __restrict__ Wattn,
                          const float* __restrict__ battn)
{
    int k = blockIdx.x;
    __shared__ float sac[CC];
    int tid = threadIdx.x;
    if (tid < CC) sac[tid] = ac[k * CC + tid];
    __syncthreads();
    if (tid < D2) {
        float acc = battn[k * D2 + tid];
        const float* W = Wattn + (long)k * (CC + D2) * D2 + tid;
        for (int c = 0; c < CC; c++) acc = fmaf(sac[c], W[(long)c * D2], acc);
        g_ctxbase[k][tid] = acc;
    }
}

// ============== K3b: context = tanh(base + hidden @ Wattn[:,C:,:]) ==========
__global__ void k_context(const float* __restrict__ Wattn)
{
    int k = blockIdx.x, b = blockIdx.y;
    __shared__ float shid[D2];
    int tid = threadIdx.x;
    if (tid < D2) shid[tid] = g_hidden[b][tid];
    __syncthreads();
    if (tid < D2) {
        float acc = g_ctxbase[k][tid];
        const float* W = Wattn + ((long)k * (CC + D2) + CC) * D2 + tid;
        for (int e = 0; e < D2; e++) acc = fmaf(shid[e], W[(long)e * D2], acc);
        g_context[b][k][tid] = tanhf(acc);
    }
}

// ============== K3c: fused attention + topic + classifier + reg part ========
#define TS 16
__global__ void k_attn(const float* __restrict__ Wtop, const float* __restrict__ btop,
                       const float* __restrict__ Wout, const float* __restrict__ bout,
                       float* __restrict__ out)
{
    int b = blockIdx.x;
    __shared__ float sctx[KK][D2];
    __shared__ float sE[TT][KK];
    __shared__ float sSeq[TS][D2];
    __shared__ float spool[KK][D2];
    __shared__ float sfeat[KK * THD];
    __shared__ float sred[256];
    __shared__ float snorm[KK];
    __shared__ float slog[NCLS];
    int tid = threadIdx.x;

    for (int i = tid; i < KK * D2; i += 256) sctx[i / D2][i % D2] = g_context[b][i / D2][i % D2];
    __syncthreads();

    for (int tile = 0; tile < TT / TS; tile++) {
        int t0 = tile * TS;
        for (int i = tid; i < TS * D2; i += 256)
            sSeq[i / D2][i % D2] = g_seq[b][t0 + i / D2][i % D2];
        __syncthreads();
        if (tid < TS * KK) {
            int r = tid / KK, k = tid % KK;
            float acc = 0.f;
            for (int d = 0; d < D2; d++) acc = fmaf(sSeq[r][d], sctx[k][d], acc);
            sE[t0 + r][k] = acc;
        }
        __syncthreads();
    }

    for (int k = 0; k < KK; k++) {
        float m = -1e30f;
        for (int t = tid; t < TT; t += 256) m = fmaxf(m, sE[t][k]);
        sred[tid] = m; __syncthreads();
        for (int s = 128; s > 0; s >>= 1) { if (tid < s) sred[tid] = fmaxf(sred[tid], sred[tid + s]); __syncthreads(); }
        m = sred[0]; __syncthreads();
        float sum = 0.f;
        for (int t = tid; t < TT; t += 256) { float e = expf(sE[t][k] - m); sE[t][k] = e; sum += e; }
        sred[tid] = sum; __syncthreads();
        for (int s = 128; s > 0; s >>= 1) { if (tid < s) sred[tid] += sred[tid + s]; __syncthreads(); }
        float inv = 1.f / sred[0]; __syncthreads();
        for (int t = tid; t < TT; t += 256) sE[t][k] *= inv;
        __syncthreads();
    }

    float pacc[8];
#pragma unroll
    for (int i = 0; i < 8; i++) pacc[i] = 0.f;
    for (int tile = 0; tile < TT / TS; tile++) {
        int t0 = tile * TS;
        for (int i = tid; i < TS * D2; i += 256)
            sSeq[i / D2][i % D2] = g_seq[b][t0 + i / D2][i % D2];
        __syncthreads();
#pragma unroll
        for (int i = 0; i < 8; i++) {
            int idx = tid + i * 256;
            if (idx < KK * D2) {
                int k = idx / D2, d = idx % D2;
                float a = pacc[i];
#pragma unroll
                for (int r = 0; r < TS; r++) a = fmaf(sSeq[r][d], sE[t0 + r][k], a);
                pacc[i] = a;
            }
        }
        __syncthreads();
    }
#pragma unroll
    for (int i = 0; i < 8; i++) {
        int idx = tid + i * 256;
        if (idx < KK * D2) spool[idx / D2][idx % D2] = pacc[i];
    }
    __syncthreads();

    if (tid < KK * THD) {
        int k = tid / THD, hh = tid % THD;
        float acc = btop[k * THD + hh];
        const float* W = Wtop + ((long)k * D2) * THD + hh;
        for (int d = 0; d < D2; d++) acc = fmaf(spool[k][d], W[d * THD], acc);
        sfeat[tid] = fmaxf(acc, 0.f);
    }
    if (tid >= 128 && tid < 128 + KK) {
        int k = tid - 128;
        float s = 0.f;
        for (int d = 0; d < D2; d++) { float v = sctx[k][d]; s = fmaf(v, v, s); }
        snorm[k] = fmaxf(sqrtf(s), 1e-12f);
    }
    __syncthreads();

    if (tid < NCLS) {
        float acc = bout[tid];
        for (int f = 0; f < KK * THD; f++) acc = fmaf(sfeat[f], Wout[f * NCLS + tid], acc);
        slog[tid] = acc;
    }
    if (tid < 64) sred[tid] = 0.f;
    __syncthreads();
    if (tid < KK * KK) {
        int k = tid / KK, j = tid % KK;
        float acc = 0.f;
        for (int d = 0; d < D2; d++) acc = fmaf(sctx[k][d], sctx[j][d], acc);
        acc = acc / (snorm[k] * snorm[j]) - ((k == j) ? 1.f : 0.f);
        sred[tid] = acc * acc;
    }
    __syncthreads();
    if (tid == 0) {
        float m = slog[0];
        for (int c = 1; c < NCLS; c++) m = fmaxf(m, slog[c]);
        float s = 0.f, e[NCLS];
        for (int c = 0; c < NCLS; c++) { e[c] = expf(slog[c] - m); s += e[c]; }
        for (int c = 0; c < NCLS; c++) out[b * NCLS + c] = e[c] / s;
        float rs = 0.f;
        for (int i = 0; i < KK * KK; i++) rs += sred[i];
        g_regpart[b] = sqrtf(rs);
    }
}

// ============== K3d: reg = mean_b regpart =================================
__global__ void k_reg(float* __restrict__ out)
{
    __shared__ float sr[BB];
    int tid = threadIdx.x;
    sr[tid] = g_regpart[tid];
    __syncthreads();
    for (int s = 64; s > 0; s >>= 1) { if (tid < s) sr[tid] += sr[tid + s]; __syncthreads(); }
    if (tid == 0) out[BB * NCLS] = sr[0] / (float)BB;
}

// ===========================================================================
extern "C" void kernel_launch(void* const* d_in, const int* in_sizes, int n_in,
                              void* d_out, int out_size)
{
    const float* x      = (const float*)d_in[0];
    const float* Wih_f  = (const float*)d_in[1];
    const float* Whh_f  = (const float*)d_in[2];
    const float* bih_f  = (const float*)d_in[3];
    const float* bhh_f  = (const float*)d_in[4];
    const float* Wih_b  = (const float*)d_in[5];
    const float* Whh_b  = (const float*)d_in[6];
    const float* bih_b  = (const float*)d_in[7];
    const float* bhh_b  = (const float*)d_in[8];
    const float* ac     = (const float*)d_in[9];
    const float* Wattn  = (const float*)d_in[10];
    const float* battn  = (const float*)d_in[11];
    const float* Wtop   = (const float*)d_in[12];
    const float* btop   = (const float*)d_in[13];
    const float* Wout   = (const float*)d_in[14];
    const float* bout   = (const float*)d_in[15];
    float* out = (float*)d_out;

    cudaFuncSetAttribute(k_gemm, cudaFuncAttributeMaxDynamicSharedMemorySize, GEMM_SMEM);

    k_convA<<<(MM * (KPAD / 2) + 255) / 256, 256>>>(x);
    k_convB<<<(NPAD * (KPAD / 2) + 255) / 256, 256>>>(Wih_f, Wih_b);
    k_convBias<<<(NPAD + 255) / 256, 256>>>(bih_f, bih_b);
    k_gemm<<<dim3(MM / BM, NPAD / BN), 256, GEMM_SMEM>>>();
    k_rec<<<128, 480>>>(Whh_f, bhh_f, Whh_b, bhh_b);
    k_ctxbase<<<KK, 320>>>(ac, Wattn, battn);
    k_context<<<dim3(KK, BB), 320>>>(Wattn);
    k_attn<<<BB, 256>>>(Wtop, btop, Wout, bout, out);
    k_reg<<<1, BB>>>(out);
}